// round 5
// baseline (speedup 1.0000x reference)
#include <cuda_runtime.h>

// DentateGyrus granule-cell spike kernel.
//
// Reference algebra (verified: rel_err = 0.0 in R2):
//   spike[i] = (v + 0.5*(0.04 v^2 + 5 v + 140 - u + 10*(W@ec)[i]) >= 30) ? 1 : 0
// The reference's top-K sparsification is an identity on a binary vector
// (threshold is 1.0 or 0.0; either way mask*spike == spike), and inputs 4..7
// only touch state never returned. Pure HBM-bound GEMV (1 GiB of W).
//
// vs R2 (152.3us, DRAM 85.2%, HBM 6972 GB/s, 87.2% of spec):
//  - persistent grid (4 blocks/SM x 148 SMs), grid-stride over row-groups:
//    ec staged once per resident block instead of 4096 times (~112 MB less
//    L2 traffic), no wave transitions.
//  - __ldcs on the W stream: W has zero reuse; evict-first keeps L1/L2 for
//    the ec broadcast lines.

constexpr int ENTRY   = 8192;          // ec dimension (fixed by problem)
constexpr int THREADS = 256;
constexpr int WARPS   = THREADS / 32;  // 8 rows per row-group
constexpr int SMS     = 148;           // B200 sm_100a
constexpr int BLOCKS  = SMS * 4;       // 4 resident blocks/SM (reg-bound occ)

__global__ __launch_bounds__(THREADS, 4)
void dentate_gyrus_kernel(const float* __restrict__ ec,
                          const float* __restrict__ W,
                          const float* __restrict__ v_in,
                          const float* __restrict__ u_in,
                          float* __restrict__ out,
                          int n_rows)
{
    // Stage ec (32 KB) in shared memory ONCE per resident block.
    __shared__ float4 s_ec[ENTRY / 4];
    const float4* ec4 = reinterpret_cast<const float4*>(ec);
    #pragma unroll
    for (int i = threadIdx.x; i < ENTRY / 4; i += THREADS) {
        s_ec[i] = ec4[i];
    }
    __syncthreads();

    const int warp     = threadIdx.x >> 5;
    const int lane     = threadIdx.x & 31;
    const int n_groups = (n_rows + WARPS - 1) / WARPS;

    for (int g = blockIdx.x; g < n_groups; g += gridDim.x) {
        const int row = g * WARPS + warp;
        if (row >= n_rows) continue;

        const float4* w4 = reinterpret_cast<const float4*>(W + (size_t)row * ENTRY);

        // 2048 float4 per row; 64 iterations per lane at stride 32.
        // Unroll 16 -> 16 independent 16B streaming loads in flight per lane.
        float acc = 0.0f;
        #pragma unroll 16
        for (int j = lane; j < ENTRY / 4; j += 32) {
            const float4 a = __ldcs(&w4[j]);   // evict-first streaming load
            const float4 b = s_ec[j];
            acc = fmaf(a.x, b.x, acc);
            acc = fmaf(a.y, b.y, acc);
            acc = fmaf(a.z, b.z, acc);
            acc = fmaf(a.w, b.w, acc);
        }

        // Warp tree reduction.
        #pragma unroll
        for (int off = 16; off > 0; off >>= 1)
            acc += __shfl_xor_sync(0xFFFFFFFFu, acc, off);

        if (lane == 0) {
            const float I  = acc * 10.0f;
            const float v  = __ldg(&v_in[row]);
            const float u  = __ldg(&u_in[row]);
            const float dv = 0.04f * v * v + 5.0f * v + 140.0f - u + I;
            const float vn = fmaf(dv, 0.5f, v);          // DT = 0.5
            out[row] = (vn >= 30.0f) ? 1.0f : 0.0f;
        }
    }
}

extern "C" void kernel_launch(void* const* d_in, const int* in_sizes, int n_in,
                              void* d_out, int out_size)
{
    // metadata order:
    // 0: ec_spike_vector (8192)
    // 1: W (32768*8192)
    // 2: membrane_potential (32768)
    // 3: recovery_variable (32768)
    // 4..7: dead for the returned output
    const float* ec = (const float*)d_in[0];
    const float* W  = (const float*)d_in[1];
    const float* v  = (const float*)d_in[2];
    const float* u  = (const float*)d_in[3];
    float* out      = (float*)d_out;

    const int n_rows = in_sizes[2];   // 32768
    dentate_gyrus_kernel<<<BLOCKS, THREADS>>>(ec, W, v, u, out, n_rows);
}